// round 2
// baseline (speedup 1.0000x reference)
#include <cuda_runtime.h>

// Problem constants
#define DIMK   256        // K of GEMM (h feature dim)
#define NOUT   512        // N of GEMM (2*dim)
#define MROWS  32768      // B*N nodes
#define NEMB   255        // embedding width (dim-1)
#define NEDGE  4194304    // E = 256*128*128

// GEMM tiling
#define BM 128
#define BN 128
#define BKT 16
#define TM 8
#define TN 8

// ---------------------------------------------------------------------------
// Fused h-construction + SGEMM:  out[m][n] = sum_k h[m][k]*W[k][n] + b[n]
// h[m][0] = charges[m]*mask[m]; h[m][1+j] = emb[cat[m]][j]*mask[m]
// ---------------------------------------------------------------------------
__global__ __launch_bounds__(256) void gemm_h_kernel(
    const float* __restrict__ charges,
    const int*   __restrict__ cats,
    const float* __restrict__ nmask,
    const float* __restrict__ emb,    // [100,255] row-major
    const float* __restrict__ W,      // [256,512] row-major
    const float* __restrict__ bias,   // [512]
    float*       __restrict__ out)    // [32768,512]
{
    __shared__ float As[BKT][BM];
    __shared__ float Bs[BKT][BN];
    __shared__ int   s_cat[BM];
    __shared__ float s_chm[BM];   // charge * mask
    __shared__ float s_msk[BM];

    const int bm  = blockIdx.y * BM;
    const int bn  = blockIdx.x * BN;
    const int tid = threadIdx.x;

    if (tid < BM) {
        int r = bm + tid;
        float m = nmask[r];
        s_cat[tid] = cats[r];
        s_msk[tid] = m;
        s_chm[tid] = charges[r] * m;
    }
    __syncthreads();

    float acc[TM][TN];
    #pragma unroll
    for (int i = 0; i < TM; i++)
        #pragma unroll
        for (int j = 0; j < TN; j++) acc[i][j] = 0.f;

    const int ty = tid >> 4;      // 0..15 -> row group
    const int tx = tid & 15;      // 0..15 -> col group

    for (int kb = 0; kb < DIMK; kb += BKT) {
        // ---- load A tile (fused h gather): 128x16 = 2048 elems, 8/thread.
        // e = tid + j*256: consecutive threads hit consecutive k -> coalesced
        // reads within one emb row.
        #pragma unroll
        for (int j = 0; j < 8; j++) {
            int e  = tid + j * 256;
            int kk = e & (BKT - 1);       // 0..15
            int m  = e >> 4;              // 0..127
            int k  = kb + kk;
            float v;
            if (k == 0) v = s_chm[m];
            else        v = __ldg(&emb[s_cat[m] * NEMB + (k - 1)]) * s_msk[m];
            As[kk][m] = v;
        }
        // ---- load B tile: W[kb+k][bn+n], n fastest -> coalesced
        #pragma unroll
        for (int j = 0; j < 8; j++) {
            int e = tid + j * 256;
            int n = e & (BN - 1);
            int k = e >> 7;
            Bs[k][n] = W[(kb + k) * NOUT + bn + n];
        }
        __syncthreads();

        #pragma unroll
        for (int k = 0; k < BKT; k++) {
            float a[TM], b[TN];
            // vectorized smem reads
            *reinterpret_cast<float4*>(&a[0]) = *reinterpret_cast<const float4*>(&As[k][ty * TM]);
            *reinterpret_cast<float4*>(&a[4]) = *reinterpret_cast<const float4*>(&As[k][ty * TM + 4]);
            *reinterpret_cast<float4*>(&b[0]) = *reinterpret_cast<const float4*>(&Bs[k][tx * TN]);
            *reinterpret_cast<float4*>(&b[4]) = *reinterpret_cast<const float4*>(&Bs[k][tx * TN + 4]);
            #pragma unroll
            for (int i = 0; i < TM; i++)
                #pragma unroll
                for (int j = 0; j < TN; j++)
                    acc[i][j] = fmaf(a[i], b[j], acc[i][j]);
        }
        __syncthreads();
    }

    // epilogue: bias add + vectorized store
    #pragma unroll
    for (int i = 0; i < TM; i++) {
        int row = bm + ty * TM + i;
        #pragma unroll
        for (int j = 0; j < TN; j += 4) {
            int col = bn + tx * TN + j;
            float4 v;
            v.x = acc[i][j + 0] + bias[col + 0];
            v.y = acc[i][j + 1] + bias[col + 1];
            v.z = acc[i][j + 2] + bias[col + 2];
            v.w = acc[i][j + 3] + bias[col + 3];
            *reinterpret_cast<float4*>(&out[(size_t)row * NOUT + col]) = v;
        }
    }
}

// ---------------------------------------------------------------------------
// Edge kernel: radial + coord_diff
// ---------------------------------------------------------------------------
__global__ __launch_bounds__(256) void edge_kernel(
    const float* __restrict__ x,      // [32768,3]
    const int*   __restrict__ edges,  // [2, E]
    float*       __restrict__ radial, // [E]
    float*       __restrict__ cd)     // [E,3]
{
    int e = blockIdx.x * 256 + threadIdx.x;
    if (e >= NEDGE) return;
    int r = __ldg(&edges[e]);
    int c = __ldg(&edges[NEDGE + e]);
    float dx = __ldg(&x[3 * r + 0]) - __ldg(&x[3 * c + 0]);
    float dy = __ldg(&x[3 * r + 1]) - __ldg(&x[3 * c + 1]);
    float dz = __ldg(&x[3 * r + 2]) - __ldg(&x[3 * c + 2]);
    float rad = dx * dx + dy * dy + dz * dz;
    float inv = 1.0f / (sqrtf(rad + 1e-8f) + 1.0f);
    radial[e]       = rad;
    cd[3 * e + 0]   = dx * inv;
    cd[3 * e + 1]   = dy * inv;
    cd[3 * e + 2]   = dz * inv;
}

// ---------------------------------------------------------------------------
// Launch
// inputs: 0 x, 1 categories, 2 charges, 3 edges, 4 node_mask, 5 edge_mask,
//         6 emb_table, 7 W, 8 b_lin
// output layout (flat f32): parameters [32768*512] | radial [E] | coord_diff [E*3]
// ---------------------------------------------------------------------------
extern "C" void kernel_launch(void* const* d_in, const int* in_sizes, int n_in,
                              void* d_out, int out_size)
{
    const float* x        = (const float*)d_in[0];
    const int*   cats     = (const int*)  d_in[1];
    const float* charges  = (const float*)d_in[2];
    const int*   edges    = (const int*)  d_in[3];
    const float* nmask    = (const float*)d_in[4];
    // d_in[5] edge_mask unused by the returned outputs
    const float* emb      = (const float*)d_in[6];
    const float* W        = (const float*)d_in[7];
    const float* bias     = (const float*)d_in[8];

    float* out        = (float*)d_out;
    float* out_params = out;                                  // 16,777,216
    float* out_radial = out + (size_t)MROWS * NOUT;           // +4,194,304
    float* out_cd     = out_radial + NEDGE;                   // +12,582,912

    dim3 ggrid(NOUT / BN, MROWS / BM);   // (4, 256)
    gemm_h_kernel<<<ggrid, 256>>>(charges, cats, nmask, emb, W, bias, out_params);

    edge_kernel<<<NEDGE / 256, 256>>>(x, edges, out_radial, out_cd);
}

// round 3
// speedup vs baseline: 1.1350x; 1.1350x over previous
#include <cuda_runtime.h>

#define DIMK   256
#define NOUT   512
#define MROWS  32768
#define NEMB   255
#define NEDGE  4194304

typedef unsigned long long u64;

// scratch: padded x for 16B-aligned gathers
__device__ float4 g_xpad[MROWS];

__device__ __forceinline__ u64 pack2(float x) {
    u64 r; asm("mov.b64 %0,{%1,%1};" : "=l"(r) : "f"(x)); return r;
}
__device__ __forceinline__ void fma2(u64& d, u64 a, u64 b) {
    asm("fma.rn.f32x2 %0,%1,%2,%0;" : "+l"(d) : "l"(a), "l"(b));
}
__device__ __forceinline__ void unpack2(u64 v, float& lo, float& hi) {
    asm("mov.b64 {%0,%1},%2;" : "=f"(lo), "=f"(hi) : "l"(v));
}

// ---------------------------------------------------------------------------
// pad x -> float4 scratch
// ---------------------------------------------------------------------------
__global__ __launch_bounds__(256) void pad_x_kernel(const float* __restrict__ x) {
    int i = blockIdx.x * 256 + threadIdx.x;
    if (i < MROWS)
        g_xpad[i] = make_float4(x[3 * i], x[3 * i + 1], x[3 * i + 2], 0.f);
}

// ---------------------------------------------------------------------------
// Fused kernel: GEMM blocks (bidx%3==0, 1024 of them) + edge blocks (2048)
// interleaved so both kinds co-reside on every SM wave.
// ---------------------------------------------------------------------------
__global__ __launch_bounds__(256, 2) void fused_kernel(
    const float* __restrict__ charges,
    const int*   __restrict__ cats,
    const float* __restrict__ nmask,
    const float* __restrict__ emb,     // [100,255]
    const float* __restrict__ W,       // [256,512]
    const float* __restrict__ bias,    // [512]
    const int*   __restrict__ edges,   // [2,E]
    float*       __restrict__ out_p,   // [32768,512]
    float*       __restrict__ radial,  // [E]
    float*       __restrict__ cd)      // [E,3]
{
    __shared__ __align__(16) float As[2][16][128];
    __shared__ __align__(16) float Bs[2][16][128];
    __shared__ int   s_cat[128];
    __shared__ float s_chm[128];
    __shared__ float s_msk[128];

    const int tid  = threadIdx.x;
    const int bidx = blockIdx.x;

    if (bidx % 3 == 0) {
        // =================== GEMM path ===================
        const int g  = bidx / 3;           // 0..1023
        const int bn = (g & 3) * 128;
        const int bm = (g >> 2) * 128;

        if (tid < 128) {
            int r = bm + tid;
            float m = nmask[r];
            s_cat[tid] = cats[r];
            s_msk[tid] = m;
            s_chm[tid] = charges[r] * m;
        }
        __syncthreads();

        const int ty = tid >> 4;     // 0..15
        const int tx = tid & 15;     // 0..15
        const int n4 = (tid & 31) * 4;
        const int bk = tid >> 5;     // 0..7

        float  aReg[8];
        float4 bReg[2];

        u64 acc[4][8];
        #pragma unroll
        for (int i = 0; i < 4; i++)
            #pragma unroll
            for (int j = 0; j < 8; j++) acc[i][j] = 0ull;

        // ---- tile loaders (global -> regs) ----
        auto loadT = [&](int kb) {
            #pragma unroll
            for (int j = 0; j < 8; j++) {
                int e  = tid + j * 256;
                int kk = e & 15;
                int m  = e >> 4;
                int k  = kb * 16 + kk;
                aReg[j] = (k == 0) ? s_chm[m]
                                   : __ldg(&emb[s_cat[m] * NEMB + (k - 1)]) * s_msk[m];
            }
            bReg[0] = *(const float4*)&W[(kb * 16 + bk    ) * NOUT + bn + n4];
            bReg[1] = *(const float4*)&W[(kb * 16 + bk + 8) * NOUT + bn + n4];
        };
        auto storeT = [&](int buf) {
            #pragma unroll
            for (int j = 0; j < 8; j++) {
                int e = tid + j * 256;
                As[buf][e & 15][e >> 4] = aReg[j];
            }
            *(float4*)&Bs[buf][bk    ][n4] = bReg[0];
            *(float4*)&Bs[buf][bk + 8][n4] = bReg[1];
        };

        loadT(0);
        storeT(0);
        __syncthreads();

        int cur = 0;
        for (int kb = 0; kb < 16; kb++) {
            if (kb < 15) loadT(kb + 1);          // prefetch while computing
            #pragma unroll
            for (int k = 0; k < 16; k++) {
                ulonglong2 av0 = *(const ulonglong2*)&As[cur][k][ty * 8];
                ulonglong2 av1 = *(const ulonglong2*)&As[cur][k][ty * 8 + 4];
                float4 b0 = *(const float4*)&Bs[cur][k][tx * 8];
                float4 b1 = *(const float4*)&Bs[cur][k][tx * 8 + 4];
                u64 ap[4] = { av0.x, av0.y, av1.x, av1.y };
                u64 bd[8] = { pack2(b0.x), pack2(b0.y), pack2(b0.z), pack2(b0.w),
                              pack2(b1.x), pack2(b1.y), pack2(b1.z), pack2(b1.w) };
                #pragma unroll
                for (int ip = 0; ip < 4; ip++)
                    #pragma unroll
                    for (int j = 0; j < 8; j++)
                        fma2(acc[ip][j], ap[ip], bd[j]);
            }
            if (kb < 15) {
                storeT(cur ^ 1);
                __syncthreads();
                cur ^= 1;
            }
        }

        // ---- epilogue: unpack, bias, vectorized store ----
        const float4 bb0 = *(const float4*)&bias[bn + tx * 8];
        const float4 bb1 = *(const float4*)&bias[bn + tx * 8 + 4];
        #pragma unroll
        for (int ip = 0; ip < 4; ip++) {
            int r0 = bm + ty * 8 + ip * 2;
            float lo[8], hi[8];
            #pragma unroll
            for (int j = 0; j < 8; j++) unpack2(acc[ip][j], lo[j], hi[j]);

            float4 v;
            size_t o0 = (size_t)r0 * NOUT + bn + tx * 8;
            v.x = lo[0] + bb0.x; v.y = lo[1] + bb0.y; v.z = lo[2] + bb0.z; v.w = lo[3] + bb0.w;
            *(float4*)&out_p[o0] = v;
            v.x = lo[4] + bb1.x; v.y = lo[5] + bb1.y; v.z = lo[6] + bb1.z; v.w = lo[7] + bb1.w;
            *(float4*)&out_p[o0 + 4] = v;

            size_t o1 = o0 + NOUT;
            v.x = hi[0] + bb0.x; v.y = hi[1] + bb0.y; v.z = hi[2] + bb0.z; v.w = hi[3] + bb0.w;
            *(float4*)&out_p[o1] = v;
            v.x = hi[4] + bb1.x; v.y = hi[5] + bb1.y; v.z = hi[6] + bb1.z; v.w = hi[7] + bb1.w;
            *(float4*)&out_p[o1 + 4] = v;
        }
    } else {
        // =================== edge path ===================
        const int eid  = bidx - (bidx + 2) / 3;   // 0..2047
        const int base = eid * 2048;              // 2048 edges per block
        float* stage = &As[0][0][0];              // 1536 floats staging

        #pragma unroll 1
        for (int r = 0; r < 4; r++) {
            int e0 = base + r * 512 + tid;
            int e1 = e0 + 256;
            int ra = __ldg(&edges[e0]);
            int rb = __ldg(&edges[e1]);
            int ca = __ldg(&edges[NEDGE + e0]);
            int cb = __ldg(&edges[NEDGE + e1]);
            float4 pa = __ldg(&g_xpad[ra]);
            float4 pb = __ldg(&g_xpad[rb]);
            float4 qa = __ldg(&g_xpad[ca]);
            float4 qb = __ldg(&g_xpad[cb]);

            float dax = pa.x - qa.x, day = pa.y - qa.y, daz = pa.z - qa.z;
            float dbx = pb.x - qb.x, dby = pb.y - qb.y, dbz = pb.z - qb.z;
            float rada = dax * dax + day * day + daz * daz;
            float radb = dbx * dbx + dby * dby + dbz * dbz;
            float inva = 1.0f / (sqrtf(rada + 1e-8f) + 1.0f);
            float invb = 1.0f / (sqrtf(radb + 1e-8f) + 1.0f);

            radial[e0] = rada;
            radial[e1] = radb;

            stage[tid * 3 + 0] = dax * inva;
            stage[tid * 3 + 1] = day * inva;
            stage[tid * 3 + 2] = daz * inva;
            stage[(tid + 256) * 3 + 0] = dbx * invb;
            stage[(tid + 256) * 3 + 1] = dby * invb;
            stage[(tid + 256) * 3 + 2] = dbz * invb;
            __syncthreads();

            // 1536 staged floats = 384 float4 -> fully coalesced store
            float4* dst = (float4*)(cd + (size_t)(base + r * 512) * 3);
            const float4* s4 = (const float4*)stage;
            dst[tid] = s4[tid];
            if (tid < 128) dst[256 + tid] = s4[256 + tid];
            __syncthreads();
        }
    }
}

// ---------------------------------------------------------------------------
// inputs: 0 x, 1 categories, 2 charges, 3 edges, 4 node_mask, 5 edge_mask,
//         6 emb_table, 7 W, 8 b_lin
// output: parameters [32768*512] | radial [E] | coord_diff [E*3]
// ---------------------------------------------------------------------------
extern "C" void kernel_launch(void* const* d_in, const int* in_sizes, int n_in,
                              void* d_out, int out_size)
{
    const float* x       = (const float*)d_in[0];
    const int*   cats    = (const int*)  d_in[1];
    const float* charges = (const float*)d_in[2];
    const int*   edges   = (const int*)  d_in[3];
    const float* nmask   = (const float*)d_in[4];
    const float* emb     = (const float*)d_in[6];
    const float* W       = (const float*)d_in[7];
    const float* bias    = (const float*)d_in[8];

    float* out        = (float*)d_out;
    float* out_params = out;
    float* out_radial = out + (size_t)MROWS * NOUT;
    float* out_cd     = out_radial + NEDGE;

    pad_x_kernel<<<MROWS / 256, 256>>>(x);
    fused_kernel<<<3072, 256>>>(charges, cats, nmask, emb, W, bias, edges,
                                out_params, out_radial, out_cd);
}

// round 5
// speedup vs baseline: 1.9715x; 1.7371x over previous
#include <cuda_runtime.h>
#include <cstdint>

#define DIMK   256
#define NOUT   512
#define MROWS  32768
#define NEMB   255
#define NEDGE  4194304

typedef unsigned int u32;

// device scratch
__device__ float4 g_xpad[MROWS];
__device__ u32    g_Wfrag[NOUT * DIMK];   // W in tf32, mma-fragment order

// smem byte offsets (GEMM path)
#define SM_CAT  0
#define SM_CHM  512
#define SM_MSK  1024
#define SM_A0   1536
#define SM_A1   17920
#define SM_B0   34304
#define SM_B1   50688
#define SM_SIZE 67072

__device__ __forceinline__ u32 f2tf32(float v) {
    u32 r; asm("cvt.rna.tf32.f32 %0, %1;" : "=r"(r) : "f"(v)); return r;
}

__device__ __forceinline__ void mma_tf32(float* c, uint4 a, uint2 b) {
    asm volatile(
        "mma.sync.aligned.m16n8k8.row.col.f32.tf32.tf32.f32 "
        "{%0,%1,%2,%3}, {%4,%5,%6,%7}, {%8,%9}, {%0,%1,%2,%3};"
        : "+f"(c[0]), "+f"(c[1]), "+f"(c[2]), "+f"(c[3])
        : "r"(a.x), "r"(a.y), "r"(a.z), "r"(a.w), "r"(b.x), "r"(b.y));
}

// ---------------------------------------------------------------------------
// Prologue:
//   blocks 0..127  : build g_Wfrag — W transposed+tf32, laid out so the GEMM's
//                    B tile loader is a flat contiguous copy.
//     fidx layout: [nb(4)][kc(8)][tile_n(16)][tile_k(4)][lane(32)][reg(2)]
//     n = nb*128 + tile_n*8 + lane/4
//     k = kc*32 + tile_k*8 + (lane&3) + 4*reg
//   blocks 128..255: pad x -> float4
// ---------------------------------------------------------------------------
__global__ __launch_bounds__(256) void prologue_kernel(
    const float* __restrict__ x, const float* __restrict__ W)
{
    int bid = blockIdx.x, tid = threadIdx.x;
    if (bid < 128) {
        #pragma unroll
        for (int i = 0; i < 4; i++) {
            int fidx  = bid * 1024 + i * 256 + tid;
            int reg   = fidx & 1;
            int lane  = (fidx >> 1) & 31;
            int tk    = (fidx >> 6) & 3;
            int tn    = (fidx >> 8) & 15;
            int kc    = (fidx >> 12) & 7;
            int nb    = fidx >> 15;
            int n = nb * 128 + tn * 8 + (lane >> 2);
            int k = kc * 32 + tk * 8 + (lane & 3) + 4 * reg;
            g_Wfrag[fidx] = f2tf32(W[k * NOUT + n]);
        }
    } else {
        int i = (bid - 128) * 256 + tid;
        if (i < MROWS)
            g_xpad[i] = make_float4(x[3 * i], x[3 * i + 1], x[3 * i + 2], 0.f);
    }
}

// ---------------------------------------------------------------------------
// Fused: tf32 mma.sync GEMM blocks (bidx%3==0, 1024) + edge blocks (2048)
// GEMM: 128x128 tile, 8 warps (4 M x 2 N), warp tile 32x64,
//       mma m16n8k8, K staged in 8 chunks of 32, double-buffered smem,
//       A & B stored in fragment order (conflict-free LDS.128 / LDS.64).
// ---------------------------------------------------------------------------
__global__ __launch_bounds__(256, 2) void fused_kernel(
    const float* __restrict__ charges,
    const int*   __restrict__ cats,
    const float* __restrict__ nmask,
    const float* __restrict__ emb,     // [100,255]
    const float* __restrict__ bias,    // [512]
    const int*   __restrict__ edges,   // [2,E]
    float*       __restrict__ out_p,   // [32768,512]
    float*       __restrict__ radial,  // [E]
    float*       __restrict__ cd)      // [E,3]
{
    extern __shared__ char sm[];
    const int tid  = threadIdx.x;
    const int bidx = blockIdx.x;

    if (bidx % 3 == 0) {
        // =========================== GEMM ===========================
        const int g  = bidx / 3;
        const int bn = (g & 3) * 128;
        const int bm = (g >> 2) * 128;
        const int wid = tid >> 5;
        const int lid = tid & 31;
        const int warp_m = wid & 3;     // 0..3
        const int warp_n = wid >> 2;    // 0..1

        int*   s_cat = (int*)  (sm + SM_CAT);
        float* s_chm = (float*)(sm + SM_CHM);
        float* s_msk = (float*)(sm + SM_MSK);

        if (tid < 128) {
            int r = bm + tid;
            float m = nmask[r];
            s_cat[tid] = cats[r];
            s_msk[tid] = m;
            s_chm[tid] = charges[r] * m;
        }
        __syncthreads();

        u32* Abuf[2] = { (u32*)(sm + SM_A0), (u32*)(sm + SM_A1) };
        u32* Bbuf[2] = { (u32*)(sm + SM_B0), (u32*)(sm + SM_B1) };

        // A loader: fused h gather -> tf32 -> fragment layout
        //   frag float idx = ((m>>4)*4 + (k>>3))*128 + ((m&7)*4 + (k&3))*4
        //                    + ((m>>3)&1) + 2*((k>>2)&1)
        auto loadA = [&](int c, int buf) {
            u32* Ab = Abuf[buf];
            #pragma unroll
            for (int i = 0; i < 16; i++) {
                int e  = tid + i * 256;
                int k  = e & 31;
                int m  = e >> 5;
                int gk = c * 32 + k;
                float v = (gk == 0) ? s_chm[m]
                                    : __ldg(&emb[s_cat[m] * NEMB + gk - 1]) * s_msk[m];
                int off = (((m >> 4) * 4 + (k >> 3)) * 32 + ((m & 7) * 4 + (k & 3))) * 4
                          + ((m >> 3) & 1) + 2 * ((k >> 2) & 1);
                Ab[off] = f2tf32(v);
            }
        };
        // B loader: flat contiguous copy of one pre-permuted 16KB chunk
        auto loadB = [&](int c, int buf) {
            const uint4* src = (const uint4*)&g_Wfrag[((bn >> 7) * 8 + c) * 4096];
            uint4* dst = (uint4*)Bbuf[buf];
            #pragma unroll
            for (int i = 0; i < 4; i++) {
                int e = tid + i * 256;
                dst[e] = __ldg(&src[e]);
            }
        };

        float acc[2][8][4];
        #pragma unroll
        for (int t = 0; t < 2; t++)
            #pragma unroll
            for (int j = 0; j < 8; j++)
                #pragma unroll
                for (int q = 0; q < 4; q++) acc[t][j][q] = 0.f;

        loadA(0, 0);
        loadB(0, 0);
        __syncthreads();

        #pragma unroll 1
        for (int c = 0; c < 8; c++) {
            int buf = c & 1;
            if (c < 7) { loadA(c + 1, buf ^ 1); loadB(c + 1, buf ^ 1); }

            const u32* Asm = Abuf[buf];
            const u32* Bsm = Bbuf[buf];
            #pragma unroll
            for (int tk = 0; tk < 4; tk++) {
                uint4 afr[2];
                #pragma unroll
                for (int t = 0; t < 2; t++)
                    afr[t] = *(const uint4*)&Asm[(((warp_m * 2 + t) * 4 + tk) * 32 + lid) * 4];
                uint2 bfr[8];
                #pragma unroll
                for (int j = 0; j < 8; j++)
                    bfr[j] = *(const uint2*)&Bsm[(((warp_n * 8 + j) * 4 + tk) * 32 + lid) * 2];
                #pragma unroll
                for (int t = 0; t < 2; t++)
                    #pragma unroll
                    for (int j = 0; j < 8; j++)
                        mma_tf32(acc[t][j], afr[t], bfr[j]);
            }
            __syncthreads();
        }

        // epilogue: bias + direct float2 stores
        #pragma unroll
        for (int t = 0; t < 2; t++) {
            int m0 = bm + warp_m * 32 + t * 16 + (lid >> 2);
            #pragma unroll
            for (int j = 0; j < 8; j++) {
                int col = bn + warp_n * 64 + j * 8 + (lid & 3) * 2;
                float2 bv = __ldg((const float2*)&bias[col]);
                float2 v0, v1;
                v0.x = acc[t][j][0] + bv.x; v0.y = acc[t][j][1] + bv.y;
                v1.x = acc[t][j][2] + bv.x; v1.y = acc[t][j][3] + bv.y;
                *(float2*)&out_p[(size_t)m0 * NOUT + col] = v0;
                *(float2*)&out_p[(size_t)(m0 + 8) * NOUT + col] = v1;
            }
        }
    } else {
        // =========================== edges ===========================
        const int eid  = bidx - (bidx + 2) / 3;   // 0..2047
        const int base = eid * 2048;
        float* stage = (float*)sm;                // 1536 floats

        #pragma unroll 1
        for (int r = 0; r < 4; r++) {
            int e0 = base + r * 512 + tid;
            int e1 = e0 + 256;
            int ra = __ldg(&edges[e0]);
            int rb = __ldg(&edges[e1]);
            int ca = __ldg(&edges[NEDGE + e0]);
            int cb = __ldg(&edges[NEDGE + e1]);
            float4 pa = __ldg(&g_xpad[ra]);
            float4 pb = __ldg(&g_xpad[rb]);
            float4 qa = __ldg(&g_xpad[ca]);
            float4 qb = __ldg(&g_xpad[cb]);

            float dax = pa.x - qa.x, day = pa.y - qa.y, daz = pa.z - qa.z;
            float dbx = pb.x - qb.x, dby = pb.y - qb.y, dbz = pb.z - qb.z;
            float rada = dax * dax + day * day + daz * daz;
            float radb = dbx * dbx + dby * dby + dbz * dbz;
            float inva = 1.0f / (sqrtf(rada + 1e-8f) + 1.0f);
            float invb = 1.0f / (sqrtf(radb + 1e-8f) + 1.0f);

            radial[e0] = rada;
            radial[e1] = radb;

            stage[tid * 3 + 0] = dax * inva;
            stage[tid * 3 + 1] = day * inva;
            stage[tid * 3 + 2] = daz * inva;
            stage[(tid + 256) * 3 + 0] = dbx * invb;
            stage[(tid + 256) * 3 + 1] = dby * invb;
            stage[(tid + 256) * 3 + 2] = dbz * invb;
            __syncthreads();

            // 1536 floats = 384 float4 coalesced
            float4* dst = (float4*)(cd + (size_t)(base + r * 512) * 3);
            const float4* s4 = (const float4*)stage;
            dst[tid] = s4[tid];
            if (tid < 128) dst[256 + tid] = s4[256 + tid];
            __syncthreads();
        }
    }
}

// ---------------------------------------------------------------------------
// inputs: 0 x, 1 categories, 2 charges, 3 edges, 4 node_mask, 5 edge_mask,
//         6 emb_table, 7 W, 8 b_lin
// output: parameters [32768*512] | radial [E] | coord_diff [E*3]
// ---------------------------------------------------------------------------
extern "C" void kernel_launch(void* const* d_in, const int* in_sizes, int n_in,
                              void* d_out, int out_size)
{
    const float* x       = (const float*)d_in[0];
    const int*   cats    = (const int*)  d_in[1];
    const float* charges = (const float*)d_in[2];
    const int*   edges   = (const int*)  d_in[3];
    const float* nmask   = (const float*)d_in[4];
    const float* emb     = (const float*)d_in[6];
    const float* W       = (const float*)d_in[7];
    const float* bias    = (const float*)d_in[8];

    float* out        = (float*)d_out;
    float* out_params = out;
    float* out_radial = out + (size_t)MROWS * NOUT;
    float* out_cd     = out_radial + NEDGE;

    cudaFuncSetAttribute(fused_kernel, cudaFuncAttributeMaxDynamicSharedMemorySize, SM_SIZE);

    prologue_kernel<<<256, 256>>>(x, W);
    fused_kernel<<<3072, 256, SM_SIZE>>>(charges, cats, nmask, emb, bias, edges,
                                         out_params, out_radial, out_cd);
}